// round 15
// baseline (speedup 1.0000x reference)
#include <cuda_runtime.h>
#include <cuda_fp16.h>
#include <math.h>

// Problem constants
constexpr int Bc   = 2;
constexpr int Tc   = 2048;
constexpr int Ec   = 1024;
constexpr int Hc   = 16;
constexpr int Dc   = 64;
constexpr int BHc  = Bc * Hc;      // 32
constexpr int Mtok = Bc * Tc;      // 4096
constexpr float LAMBDA_INIT = 0.4707130183435843f;  // 0.8 - 0.6*exp(-0.6)
constexpr float EPSc = 1e-5f;
constexpr size_t SLAB = (size_t)BHc * Tc * Dc;      // 4M elems

// Scratch (device globals: allocation-free rule)
__device__ __half g_nh[(size_t)Mtok * Ec];
__device__ __half g_xh[(size_t)Mtok * Ec];
__device__ __half g_wh[6 * (size_t)Ec * Ec];
__device__ __half g_projh[5 * SLAB];          // q1,k1,q2,k2,v
__device__ float  g_o1 [SLAB];
__device__ float  g_o2 [SLAB];
__device__ __half g_attnh[(size_t)Mtok * Ec];
__device__ float  g_lambda;

// -------------------------------------------------------------------------
__device__ __forceinline__ unsigned pack2(float lo, float hi) {
    __half2 h = __floats2half2_rn(lo, hi);
    return *reinterpret_cast<unsigned*>(&h);
}

// fp16 mma m16n8k16, fp32 accumulate
__device__ __forceinline__ void mma_h(float* c, const unsigned* a, const unsigned* b) {
    asm volatile(
        "mma.sync.aligned.m16n8k16.row.col.f32.f16.f16.f32 "
        "{%0,%1,%2,%3}, {%4,%5,%6,%7}, {%8,%9}, {%0,%1,%2,%3};"
        : "+f"(c[0]), "+f"(c[1]), "+f"(c[2]), "+f"(c[3])
        : "r"(a[0]), "r"(a[1]), "r"(a[2]), "r"(a[3]), "r"(b[0]), "r"(b[1]));
}

__device__ __forceinline__ void cp16(unsigned saddr, const void* g) {
    asm volatile("cp.async.cg.shared.global [%0], [%1], 16;\n" :: "r"(saddr), "l"(g));
}
__device__ __forceinline__ void cp_commit() { asm volatile("cp.async.commit_group;\n"); }
template<int N> __device__ __forceinline__ void cp_wait() {
    asm volatile("cp.async.wait_group %0;\n" :: "n"(N));
}
__device__ __forceinline__ void ldmx4(unsigned* r, unsigned addr) {
    asm volatile("ldmatrix.sync.aligned.m8n8.x4.shared.b16 {%0,%1,%2,%3}, [%4];"
        : "=r"(r[0]), "=r"(r[1]), "=r"(r[2]), "=r"(r[3]) : "r"(addr));
}
__device__ __forceinline__ void ldmx4t(unsigned* r, unsigned addr) {
    asm volatile("ldmatrix.sync.aligned.m8n8.x4.trans.shared.b16 {%0,%1,%2,%3}, [%4];"
        : "=r"(r[0]), "=r"(r[1]), "=r"(r[2]), "=r"(r[3]) : "r"(addr));
}

// -------------------------------------------------------------------------
__global__ void lambda_kernel(const float* __restrict__ lq1, const float* __restrict__ lk1,
                              const float* __restrict__ lq2, const float* __restrict__ lk2)
{
    __shared__ float s1[64], s2[64];
    int t = threadIdx.x;
    s1[t] = lq1[t] * lk1[t];
    s2[t] = lq2[t] * lk2[t];
    __syncthreads();
    if (t == 0) {
        float a = 0.f, b = 0.f;
        #pragma unroll
        for (int i = 0; i < 64; i++) { a += s1[i]; b += s2[i]; }
        g_lambda = expf(a) - expf(b) + LAMBDA_INIT;
    }
}

// -------------------------------------------------------------------------
// Convert all fp32 operands to fp16 once. z selects the tensor.
// q-scaling (D^-0.5 = 0.125, exact) folded into Wq1/Wq2.
// -------------------------------------------------------------------------
__global__ __launch_bounds__(256) void cvt_all(
    const float* nsy, const float* xx,
    const float* w0, const float* w1, const float* w2,
    const float* w3, const float* w4, const float* w5,
    __half* nh, __half* xh, __half* wh)
{
    int z = blockIdx.y;
    const float* s; __half* d; int n; float scl = 1.f;
    switch (z) {
        case 0: s = nsy; d = nh; n = Mtok * Ec; break;
        case 1: s = xx;  d = xh; n = Mtok * Ec; break;
        case 2: s = w0; d = wh + 0 * (size_t)Ec * Ec; n = Ec * Ec; scl = 0.125f; break;
        case 3: s = w1; d = wh + 1 * (size_t)Ec * Ec; n = Ec * Ec; break;
        case 4: s = w2; d = wh + 2 * (size_t)Ec * Ec; n = Ec * Ec; scl = 0.125f; break;
        case 5: s = w3; d = wh + 3 * (size_t)Ec * Ec; n = Ec * Ec; break;
        case 6: s = w4; d = wh + 4 * (size_t)Ec * Ec; n = Ec * Ec; break;
        default: s = w5; d = wh + 5 * (size_t)Ec * Ec; n = Ec * Ec; break;
    }
    int n4 = n >> 2;
    for (int i = blockIdx.x * blockDim.x + threadIdx.x; i < n4; i += gridDim.x * blockDim.x) {
        float4 v = ((const float4*)s)[i];
        ((__half2*)d)[2*i]   = __floats2half2_rn(v.x * scl, v.y * scl);
        ((__half2*)d)[2*i+1] = __floats2half2_rn(v.z * scl, v.w * scl);
    }
}

// -------------------------------------------------------------------------
// Pipelined fp16 NT HGEMM (unchanged from R12).
// -------------------------------------------------------------------------
constexpr int TILEB = 128 * 80;
constexpr int HG_SMEM = 3 * 2 * TILEB;

template<int MODE>
__global__ __launch_bounds__(256, 2) void hgemm(
    const __half* __restrict__ Nbase, const __half* __restrict__ Xbase,
    const __half* __restrict__ Wbase, float* __restrict__ Cf,
    __half* __restrict__ Cproj, int K, float scale)
{
    extern __shared__ char dynsm[];
    const unsigned sbase = (unsigned)__cvta_generic_to_shared(dynsm);

    const int z = blockIdx.z;
    const __half* Aop;
    const __half* Wop;
    __half* Cp = nullptr;
    if (MODE == 1) {
        Aop = (z == 2 || z == 3) ? Xbase : Nbase;
        Wop = Wbase + (size_t)z * Ec * Ec;
        Cp  = Cproj + (size_t)z * SLAB;
    } else {
        Aop = Nbase;
        Wop = Wbase;
    }

    const int m0 = blockIdx.y * 128;
    const int n0 = blockIdx.x * 128;
    const int N  = gridDim.x * 128;
    const int tid  = threadIdx.x;
    const int warp = tid >> 5, lane = tid & 31;
    const int g = lane >> 2, tig = lane & 3;
    const int wm = (warp & 1) * 64;
    const int wn = (warp >> 1) * 32;

    auto load_stage = [&](int kt, int s) {
        unsigned sa = sbase + s * (2 * TILEB);
        unsigned sb = sa + TILEB;
        const __half* Ap = Aop + (size_t)m0 * K + kt * 32;
        const __half* Wp = Wop + (size_t)n0 * K + kt * 32;
        #pragma unroll
        for (int j2 = 0; j2 < 2; j2++) {
            int cid = tid + j2 * 256;
            int row = cid >> 2, cc = cid & 3;
            cp16(sa + row * 80 + cc * 16, Ap + (size_t)row * K + cc * 8);
            cp16(sb + row * 80 + cc * 16, Wp + (size_t)row * K + cc * 8);
        }
    };

    float acc[4][4][4];
    #pragma unroll
    for (int i = 0; i < 4; i++)
        #pragma unroll
        for (int j = 0; j < 4; j++)
            #pragma unroll
            for (int r = 0; r < 4; r++) acc[i][j][r] = 0.f;

    const int KT = K / 32;
    load_stage(0, 0); cp_commit();
    load_stage(1, 1); cp_commit();

    for (int kt = 0; kt < KT; kt++) {
        cp_wait<1>();
        __syncthreads();
        if (kt + 2 < KT) load_stage(kt + 2, (kt + 2) % 3);
        cp_commit();

        const int s = kt % 3;
        unsigned aS = sbase + s * (2 * TILEB);
        unsigned bS = aS + TILEB;

        #pragma unroll
        for (int kc = 0; kc < 2; kc++) {
            unsigned a[4][4], b[4][2];
            #pragma unroll
            for (int i = 0; i < 4; i++) {
                int row = wm + i * 16 + ((lane >> 3) & 1) * 8 + (lane & 7);
                int ch  = kc * 2 + (lane >> 4);
                ldmx4(a[i], aS + row * 80 + ch * 16);
            }
            #pragma unroll
            for (int jp = 0; jp < 2; jp++) {
                int mat = lane >> 3;
                int row = wn + jp * 16 + (mat >> 1) * 8 + (lane & 7);
                int ch  = kc * 2 + (mat & 1);
                ldmx4(&b[2 * jp][0], bS + row * 80 + ch * 16);
            }
            #pragma unroll
            for (int i = 0; i < 4; i++)
                #pragma unroll
                for (int j = 0; j < 4; j++)
                    mma_h(acc[i][j], a[i], b[j]);
        }
        __syncthreads();
    }

    if (MODE == 0) {
        #pragma unroll
        for (int i = 0; i < 4; i++) {
            int r0 = m0 + wm + i * 16 + g;
            #pragma unroll
            for (int j = 0; j < 4; j++) {
                int col = n0 + wn + j * 8 + 2 * tig;
                float2 v0 = { acc[i][j][0] * scale, acc[i][j][1] * scale };
                float2 v1 = { acc[i][j][2] * scale, acc[i][j][3] * scale };
                *(float2*)(Cf + (size_t)r0 * N + col)       = v0;
                *(float2*)(Cf + (size_t)(r0 + 8) * N + col) = v1;
            }
        }
    } else {
        #pragma unroll
        for (int i = 0; i < 4; i++)
            #pragma unroll
            for (int rr = 0; rr < 2; rr++) {
                int m  = m0 + wm + i * 16 + g + rr * 8;
                int bb = m >> 11;
                int t  = m & (Tc - 1);
                #pragma unroll
                for (int j = 0; j < 4; j++) {
                    int col = n0 + wn + j * 8 + 2 * tig;
                    int h = col >> 6, d = col & (Dc - 1);
                    __half2 hv = __floats2half2_rn(acc[i][j][rr*2+0], acc[i][j][rr*2+1]);
                    *(__half2*)(Cp + ((size_t)(bb * Hc + h) * Tc + t) * Dc + d) = hv;
                }
            }
    }
}

// -------------------------------------------------------------------------
// Flash attention v3: P kept in registers (S-mma C layout == PV-mma A layout),
// no P smem staging. 256 threads, 8 warps x 32 q-rows, 64-key tiles,
// cp.async 3-stage K/V pipeline, smem 90KB -> 2 CTAs/SM.
// -------------------------------------------------------------------------
constexpr int FA_Q_OFF  = 0;                         // 256 rows x 144B
constexpr int FA_KV_OFF = 256 * 144;                 // 36864
constexpr int FA_STAGE  = 2 * 64 * 144;              // K + V per stage: 18432
constexpr int FA_BYTES  = FA_KV_OFF + 3 * FA_STAGE;  // 92160

__global__ __launch_bounds__(256, 2) void flash_attn3(
    const __half* __restrict__ Qg, const __half* __restrict__ Kg,
    const __half* __restrict__ Vg, float* __restrict__ Og)
{
    extern __shared__ char fsm[];
    const unsigned sb = (unsigned)__cvta_generic_to_shared(fsm);
    const int bh = blockIdx.y, qt = blockIdx.x;
    const int tid = threadIdx.x, lane = tid & 31, warp = tid >> 5;
    const int g = lane >> 2, tig = lane & 3;
    const int wm = warp * 32;
    const int l15 = lane & 15, l7 = lane & 7;
    const int hi16 = (lane >> 4) << 4;            // 0 or 16 (byte)
    const int hb8  = ((lane >> 3) & 1) << 4;      // 0 or 16 (byte)
    const int hr8  = ((lane >> 4) << 3);          // 0 or 8 (row)
    const int hr8b = ((lane >> 3) & 1) << 3;      // 0 or 8 (row)

    const __half* Qp = Qg + ((size_t)bh * Tc + qt * 256) * Dc;
    const __half* Kp = Kg + (size_t)bh * Tc * Dc;
    const __half* Vp = Vg + (size_t)bh * Tc * Dc;

    // Q: thread t loads row t (8 x 16B)
    {
        const __half* qr = Qp + (size_t)tid * Dc;
        unsigned qd = sb + FA_Q_OFF + tid * 144;
        #pragma unroll
        for (int j = 0; j < 8; j++) cp16(qd + j * 16, qr + j * 8);
    }
    auto load_kv = [&](int kt, int s) {
        unsigned kb = sb + FA_KV_OFF + s * FA_STAGE;
        unsigned vb = kb + 64 * 144;
        const __half* kgp = Kp + (size_t)kt * 64 * Dc;
        const __half* vgp = Vp + (size_t)kt * 64 * Dc;
        #pragma unroll
        for (int l = 0; l < 2; l++) {
            int id = tid + l * 256;
            int row = id >> 3, ch = id & 7;
            cp16(kb + row * 144 + ch * 16, kgp + (size_t)row * Dc + ch * 8);
            cp16(vb + row * 144 + ch * 16, vgp + (size_t)row * Dc + ch * 8);
        }
    };

    load_kv(0, 0); cp_commit();
    load_kv(1, 1); cp_commit();

    float o[2][8][4];
    #pragma unroll
    for (int s2 = 0; s2 < 2; s2++)
        #pragma unroll
        for (int nd = 0; nd < 8; nd++)
            #pragma unroll
            for (int r = 0; r < 4; r++) o[s2][nd][r] = 0.f;
    float mst[2][2] = { {-1e30f, -1e30f}, {-1e30f, -1e30f} };
    float sst[2][2] = { {0.f, 0.f}, {0.f, 0.f} };

    const int NKT = Tc / 64;
    for (int kt = 0; kt < NKT; kt++) {
        cp_wait<1>();
        __syncthreads();
        if (kt + 2 < NKT) load_kv(kt + 2, (kt + 2) % 3);
        cp_commit();

        const int s = kt % 3;
        const unsigned Kb = sb + FA_KV_OFF + s * FA_STAGE;
        const unsigned Vb = Kb + 64 * 144;

        // P in mma-A register layout: aP[sub][key-chunk kc][4]
        unsigned aP[2][4][4];

        // ---- S + online softmax, subtile-sequential (16 rows each) ----
        #pragma unroll
        for (int sub = 0; sub < 2; sub++) {
            float sc[8][4];
            #pragma unroll
            for (int ns = 0; ns < 8; ns++)
                #pragma unroll
                for (int r = 0; r < 4; r++) sc[ns][r] = 0.f;

            #pragma unroll
            for (int c = 0; c < 4; c++) {
                unsigned a[4];
                ldmx4(a, sb + FA_Q_OFF + (wm + sub * 16 + l15) * 144 + 32 * c + hi16);
                #pragma unroll
                for (int np = 0; np < 4; np++) {
                    unsigned bb[4];
                    ldmx4(bb, Kb + (16 * np + l7 + hr8) * 144 + 32 * c + hb8);
                    mma_h(sc[2 * np],     a, bb);
                    mma_h(sc[2 * np + 1], a, bb + 2);
                }
            }

            float mx0 = -1e30f, mx1 = -1e30f;
            #pragma unroll
            for (int ns = 0; ns < 8; ns++) {
                mx0 = fmaxf(mx0, fmaxf(sc[ns][0], sc[ns][1]));
                mx1 = fmaxf(mx1, fmaxf(sc[ns][2], sc[ns][3]));
            }
            mx0 = fmaxf(mx0, __shfl_xor_sync(0xffffffffu, mx0, 1));
            mx0 = fmaxf(mx0, __shfl_xor_sync(0xffffffffu, mx0, 2));
            mx1 = fmaxf(mx1, __shfl_xor_sync(0xffffffffu, mx1, 1));
            mx1 = fmaxf(mx1, __shfl_xor_sync(0xffffffffu, mx1, 2));
            float nm0 = fmaxf(mst[sub][0], mx0), nm1 = fmaxf(mst[sub][1], mx1);
            float cor0 = __expf(mst[sub][0] - nm0), cor1 = __expf(mst[sub][1] - nm1);
            mst[sub][0] = nm0; mst[sub][1] = nm1;

            float sum0 = 0.f, sum1 = 0.f;
            #pragma unroll
            for (int ns = 0; ns < 8; ns++) {
                float p0 = __expf(sc[ns][0] - nm0);
                float p1 = __expf(sc[ns][1] - nm0);
                float p2 = __expf(sc[ns][2] - nm1);
                float p3 = __expf(sc[ns][3] - nm1);
                sum0 += p0 + p1; sum1 += p2 + p3;
                // C layout -> A layout: rows g / g+8, keys 2tig(+1) within n8
                unsigned* dst = &aP[sub][ns >> 1][(ns & 1) << 1];
                dst[0] = pack2(p0, p1);      // row g
                dst[1] = pack2(p2, p3);      // row g+8  (a-frag slot +1)
            }
            sum0 += __shfl_xor_sync(0xffffffffu, sum0, 1);
            sum0 += __shfl_xor_sync(0xffffffffu, sum0, 2);
            sum1 += __shfl_xor_sync(0xffffffffu, sum1, 1);
            sum1 += __shfl_xor_sync(0xffffffffu, sum1, 2);
            sst[sub][0] = sst[sub][0] * cor0 + sum0;
            sst[sub][1] = sst[sub][1] * cor1 + sum1;
            #pragma unroll
            for (int nd = 0; nd < 8; nd++) {
                o[sub][nd][0] *= cor0; o[sub][nd][1] *= cor0;
                o[sub][nd][2] *= cor1; o[sub][nd][3] *= cor1;
            }
        }

        // ---- O += P . V  (V frags shared across both subtiles) ----
        // a-frag for key chunk c: {aP[.][c][0](row g,k0..1), aP[.][c][1](g+8),
        //                          aP[.][c][2](g,k8..9),    aP[.][c][3](g+8)}
        #pragma unroll
        for (int c = 0; c < 4; c++) {
            #pragma unroll
            for (int np = 0; np < 4; np++) {
                unsigned bV[4];
                ldmx4t(bV, Vb + (16 * c + l7 + hr8b) * 144 + 32 * np + hi16);
                mma_h(o[0][2 * np],     aP[0][c], bV);
                mma_h(o[0][2 * np + 1], aP[0][c], bV + 2);
                mma_h(o[1][2 * np],     aP[1][c], bV);
                mma_h(o[1][2 * np + 1], aP[1][c], bV + 2);
            }
        }
        __syncthreads();
    }

    // ---- normalize + write O (fp32, [bh][T][D]) ----
    float* ob = Og + (size_t)bh * Tc * Dc;
    #pragma unroll
    for (int sub = 0; sub < 2; sub++) {
        float inv0 = 1.0f / sst[sub][0], inv1 = 1.0f / sst[sub][1];
        int row0 = qt * 256 + wm + sub * 16 + g;
        #pragma unroll
        for (int nd = 0; nd < 8; nd++) {
            int col = nd * 8 + 2 * tig;
            float2 v0 = { o[sub][nd][0] * inv0, o[sub][nd][1] * inv0 };
            float2 v1 = { o[sub][nd][2] * inv1, o[sub][nd][3] * inv1 };
            *(float2*)(ob + (size_t)row0 * Dc + col)       = v0;
            *(float2*)(ob + (size_t)(row0 + 8) * Dc + col) = v1;
        }
    }
}

// -------------------------------------------------------------------------
// merge O1 - lam*O2, RMSNorm over D, affine, (1-lambda_init), transpose,
// write fp16 for the output projection.  One warp per (bh,t) row.
// -------------------------------------------------------------------------
__global__ __launch_bounds__(256) void merge_rms(
    const float* __restrict__ o1, const float* __restrict__ o2,
    const float* __restrict__ w, __half* __restrict__ O)
{
    int r    = blockIdx.x * 8 + (threadIdx.x >> 5);
    int lane = threadIdx.x & 31;
    float lam = g_lambda;

    const float* p1 = o1 + (size_t)r * Dc;
    const float* p2 = o2 + (size_t)r * Dc;
    float a = p1[lane]      - lam * p2[lane];
    float b = p1[lane + 32] - lam * p2[lane + 32];
    float ss = a * a + b * b;
    #pragma unroll
    for (int o = 16; o; o >>= 1) ss += __shfl_xor_sync(0xffffffffu, ss, o);
    float rr = rsqrtf(ss * (1.0f / Dc) + EPSc) * (1.0f - LAMBDA_INIT);

    int bh = r >> 11, t = r & (Tc - 1);
    int bb = bh >> 4, h = bh & (Hc - 1);
    __half* o = O + ((size_t)(bb * Tc + t)) * Ec + h * Dc;
    o[lane]      = __float2half(a * rr * w[lane]);
    o[lane + 32] = __float2half(b * rr * w[lane + 32]);
}

// -------------------------------------------------------------------------
extern "C" void kernel_launch(void* const* d_in, const int* in_sizes, int n_in,
                              void* d_out, int out_size)
{
    const float* noisy = (const float*)d_in[0];
    const float* x     = (const float*)d_in[1];
    const float* Wq1   = (const float*)d_in[2];
    const float* Wk1   = (const float*)d_in[3];
    const float* Wq2   = (const float*)d_in[4];
    const float* Wk2   = (const float*)d_in[5];
    const float* Wv    = (const float*)d_in[6];
    const float* Wout  = (const float*)d_in[7];
    const float* lq1   = (const float*)d_in[8];
    const float* lk1   = (const float*)d_in[9];
    const float* lq2   = (const float*)d_in[10];
    const float* lk2   = (const float*)d_in[11];
    const float* slw   = (const float*)d_in[12];
    float* out = (float*)d_out;

    void *nhp, *xhp, *whp, *projp, *o1p, *o2p, *attnp;
    cudaGetSymbolAddress(&nhp, g_nh);
    cudaGetSymbolAddress(&xhp, g_xh);
    cudaGetSymbolAddress(&whp, g_wh);
    cudaGetSymbolAddress(&projp, g_projh);
    cudaGetSymbolAddress(&o1p, g_o1);
    cudaGetSymbolAddress(&o2p, g_o2);
    cudaGetSymbolAddress(&attnp, g_attnh);

    static bool attr_set = false;
    if (!attr_set) {
        cudaFuncSetAttribute(flash_attn3, cudaFuncAttributeMaxDynamicSharedMemorySize, FA_BYTES);
        cudaFuncSetAttribute(hgemm<0>, cudaFuncAttributeMaxDynamicSharedMemorySize, HG_SMEM);
        cudaFuncSetAttribute(hgemm<1>, cudaFuncAttributeMaxDynamicSharedMemorySize, HG_SMEM);
        attr_set = true;
    }

    const dim3 blk(256);
    __half* nh = (__half*)nhp;
    __half* xh = (__half*)xhp;
    __half* wh = (__half*)whp;
    __half* ph = (__half*)projp;

    lambda_kernel<<<1, 64>>>(lq1, lk1, lq2, lk2);

    // fp32 -> fp16 conversion of all operands (q-scale folded into Wq1/Wq2)
    cvt_all<<<dim3(512, 8), blk>>>(noisy, x, Wq1, Wk1, Wq2, Wk2, Wv, Wout, nh, xh, wh);

    // All 5 projections in one batched launch -> head-split fp16 [B,H,T,D]
    hgemm<1><<<dim3(Ec / 128, Mtok / 128, 5), blk, HG_SMEM>>>(
        nh, xh, wh, nullptr, ph, Ec, 1.f);

    // Fused flash attention, one branch per launch
    dim3 gfa(Tc / 256, BHc);
    flash_attn3<<<gfa, blk, FA_BYTES>>>(ph + 0 * SLAB, ph + 1 * SLAB,
                                        ph + 4 * SLAB, (float*)o1p);
    flash_attn3<<<gfa, blk, FA_BYTES>>>(ph + 2 * SLAB, ph + 3 * SLAB,
                                        ph + 4 * SLAB, (float*)o2p);

    // Merge + RMSNorm -> fp16 [B,T,E]
    merge_rms<<<BHc * Tc / 8, blk>>>((const float*)o1p, (const float*)o2p, slw, (__half*)attnp);

    // Output projection -> d_out (fp32)
    hgemm<0><<<dim3(Ec / 128, Mtok / 128, 1), blk, HG_SMEM>>>(
        (const __half*)attnp, nullptr, wh + 5 * (size_t)Ec * Ec, out, nullptr, Ec, 1.f);
}